// round 15
// baseline (speedup 1.0000x reference)
#include <cuda_runtime.h>
#include <cuda_fp16.h>
#include <cstdint>

// ============================================================================
// SwapTestAttention on GB300 — Round 13:
//   R11 pipeline (2 CTAs/SM, double-buffered K, packed STS.32) + KSPL=32:
//   at 2 CTAs/SM the extra prologues overlap, and 6.74 half-length waves
//   shrink the ragged-tail idle from ~25us to ~6us.
// ============================================================================

#define NTOK 8192
#define NQB  6
#define DIM  64
#define NL   2

#define QT   128                 // queries per CTA
#define KT   64                  // keys per smem tile
#define KSPL 32                  // key splits (grid.y)
#define KEYS_PER_CTA (NTOK / KSPL)      // 256
#define NT_TILES (KEYS_PER_CTA / KT)    // 4
#define NSLOT (KSPL * 2)         // 64: splits x 2 n-warps

// smem byte offsets
#define AH_BYTES  (8 * QT * 16 * 2)          // 32768: A chunks [8][128][16] half
#define BH_BYTES  (8 * KT * 16 * 2)          // 16384 per buffer
#define BH_OFF    AH_BYTES                   // two buffers: 32768 total
#define VS_OFF    (AH_BYTES + 2 * BH_BYTES)  // V [256][12] float = 12288
#define SMEM_BYTES (VS_OFF + KEYS_PER_CTA * 12 * 4)   // 77824

// Scratch (device globals; no allocation allowed)
__device__ __half2 g_Qh[NTOK * DIM];         // [token][64] (re,im)
__device__ __half2 g_Kh[NTOK * DIM];
__device__ float   g_V[NTOK * 8];            // 6 used + pad
__device__ float   g_part[NTOK][NSLOT][8];   // token-major partials (6 acc + den + pad)
__device__ float   g_trig[3 * NL * NQB * 2 * 2];  // [role][l][q][gate][{s,c}]

__device__ __forceinline__ float shfl_x(float v, int m) {
    return __shfl_xor_sync(0xffffffffu, v, m);
}
__device__ __forceinline__ void mma_f16(float d[4],
    uint32_t a0, uint32_t a1, uint32_t a2, uint32_t a3,
    uint32_t b0, uint32_t b1)
{
    asm volatile(
        "mma.sync.aligned.m16n8k16.row.col.f32.f16.f16.f32 "
        "{%0,%1,%2,%3}, {%4,%5,%6,%7}, {%8,%9}, {%0,%1,%2,%3};"
        : "+f"(d[0]), "+f"(d[1]), "+f"(d[2]), "+f"(d[3])
        : "r"(a0), "r"(a1), "r"(a2), "r"(a3), "r"(b0), "r"(b1));
}

// k-column permutation within a 16-wide chunk: col c=2j+delta -> pos
// 4*(j&3) + 2*(j>>2) + delta. Thread's 4 needed halves are one LDS.64,
// and dims 2j, 2j+1 land adjacent -> packed STS.32 stores.
__device__ __forceinline__ int kperm_pair(int j) {   // position of col 2j
    return 4 * (j & 3) + 2 * (j >> 2);
}

// ---------------------------------------------------------------------------
// Phase 0: precompute sin/cos of all 72 param gate half-angles (3 roles).
// ---------------------------------------------------------------------------
__global__ void trig_kernel(const float* __restrict__ pq,
                            const float* __restrict__ pk,
                            const float* __restrict__ pv)
{
    int t = threadIdx.x;                 // 0..127, use 0..71
    if (t >= 3 * NL * NQB * 2) return;
    int role = t / (NL * NQB * 2);
    int g    = t - role * (NL * NQB * 2);   // ((l*6+q)*2 + gate)
    const float* p = (role == 0) ? pq : (role == 1) ? pk : pv;
    float th = p[g];
    float s, c; __sincosf(0.5f * th, &s, &c);
    g_trig[t * 2 + 0] = s;
    g_trig[t * 2 + 1] = c;
}

// ---------------------------------------------------------------------------
// Phase 1: one warp simulates one (token, role) circuit.
// ---------------------------------------------------------------------------
__global__ void __launch_bounds__(256) prep_kernel(
    const float* __restrict__ x)
{
    int gw    = (blockIdx.x * 256 + threadIdx.x) >> 5;
    int lane  = threadIdx.x & 31;
    int token = gw & (NTOK - 1);
    int role  = gw >> 13;                  // 0=Q, 1=K, 2=V
    const float* tg = g_trig + role * (NL * NQB * 2 * 2);

    float r0 = (lane == 0) ? 1.f : 0.f, i0 = 0.f, r1 = 0.f, i1 = 0.f;

    auto RYsc = [&](float s, float c, int q) {
        if (q == 0) {
            float nr0 = c*r0 - s*r1, ni0 = c*i0 - s*i1;
            float nr1 = s*r0 + c*r1, ni1 = s*i0 + c*i1;
            r0 = nr0; i0 = ni0; r1 = nr1; i1 = ni1;
        } else {
            int m = 1 << (5 - q);
            float pr0 = shfl_x(r0, m), pi0 = shfl_x(i0, m);
            float pr1 = shfl_x(r1, m), pi1 = shfl_x(i1, m);
            float sg = (lane & m) ? s : -s;
            r0 = fmaf(sg, pr0, c*r0); i0 = fmaf(sg, pi0, c*i0);
            r1 = fmaf(sg, pr1, c*r1); i1 = fmaf(sg, pi1, c*i1);
        }
    };
    auto RZsc = [&](float s, float c, int q) {
        if (q == 0) {
            float nr0 = r0*c + i0*s, ni0 = i0*c - r0*s;
            float nr1 = r1*c - i1*s, ni1 = i1*c + r1*s;
            r0 = nr0; i0 = ni0; r1 = nr1; i1 = ni1;
        } else {
            int m = 1 << (5 - q);
            float sg = (lane & m) ? s : -s;
            float nr0 = r0*c - i0*sg, ni0 = i0*c + r0*sg;
            float nr1 = r1*c - i1*sg, ni1 = i1*c + r1*sg;
            r0 = nr0; i0 = ni0; r1 = nr1; i1 = ni1;
        }
    };

    #pragma unroll
    for (int q = 0; q < NQB; q++) {
        float s, c; __sincosf(0.5f * x[token * NQB + q], &s, &c);
        RYsc(s, c, q);
    }

    #pragma unroll
    for (int l = 0; l < NL; l++) {
        #pragma unroll
        for (int q = 0; q < NQB; q++) {
            int base = ((l * NQB + q) * 2) * 2;
            RYsc(tg[base + 0], tg[base + 1], q);
            RZsc(tg[base + 2], tg[base + 3], q);
        }
        r1 = shfl_x(r1, 16); i1 = shfl_x(i1, 16);
        #pragma unroll
        for (int q = 1; q <= 4; q++) {
            int cm = 1 << (5 - q), tm = 1 << (4 - q);
            float t;
            t = shfl_x(r0, tm); if (lane & cm) r0 = t;
            t = shfl_x(i0, tm); if (lane & cm) i0 = t;
            t = shfl_x(r1, tm); if (lane & cm) r1 = t;
            t = shfl_x(i1, tm); if (lane & cm) i1 = t;
        }
        if (lane & 1) { float t = r0; r0 = r1; r1 = t; t = i0; i0 = i1; i1 = t; }
    }

    if (role < 2) {
        __half2* buf = (role == 0) ? g_Qh : g_Kh;
        buf[token * DIM + lane]      = __floats2half2_rn(r0, i0);
        buf[token * DIM + 32 + lane] = __floats2half2_rn(r1, i1);
    } else {
        float p0 = r0*r0 + i0*i0;
        float p1 = r1*r1 + i1*i1;
        float v[6];
        v[0] = p0 - p1;
        #pragma unroll
        for (int q = 1; q < 6; q++) {
            float sgn = ((lane >> (5 - q)) & 1) ? -1.f : 1.f;
            v[q] = sgn * (p0 + p1);
        }
        #pragma unroll
        for (int off = 16; off >= 1; off >>= 1) {
            #pragma unroll
            for (int q = 0; q < 6; q++) v[q] += __shfl_down_sync(0xffffffffu, v[q], off);
        }
        if (lane == 0) {
            #pragma unroll
            for (int q = 0; q < 6; q++) g_V[token * 8 + q] = v[q];
            g_V[token * 8 + 6] = 0.f;
            g_V[token * 8 + 7] = 0.f;
        }
    }
}

// ---------------------------------------------------------------------------
// Phase 2: fp16 m16n8k16 fused attention, double-buffered, 2 CTAs/SM, KSPL=32.
// ---------------------------------------------------------------------------
__global__ void __launch_bounds__(256, 2) attn_kernel()
{
    extern __shared__ char smem[];
    __half* Ah = (__half*)smem;                 // [8][QT][16]
    float*  Vs = (float*)(smem + VS_OFF);       // [256][12]

    int tid   = threadIdx.x;
    int lane  = tid & 31;
    int wid   = tid >> 5;
    int warpm = wid & 3;
    int warpn = wid >> 2;
    int rr    = lane >> 2;       // 0..7
    int cc    = lane & 3;        // 0..3
    int q0    = blockIdx.x * QT;
    int key0c = blockIdx.y * KEYS_PER_CTA;

    // ---- prologue: Q tile, K tile 0, full V chunk (packed STS.32) ----
    {
        const uint2* Qg = (const uint2*)(g_Qh + (size_t)q0 * DIM);
        for (int idx = tid; idx < QT * 32; idx += 256) {
            int q = idx >> 5, j = idx & 31;               // dims 2j, 2j+1
            uint2 v = Qg[idx];
            uint32_t rep = __byte_perm(v.x, v.y, 0x5410);
            uint32_t imp = __byte_perm(v.x, v.y, 0x7632);
            int kk = j >> 3, p = kperm_pair(j & 7);
            *(uint32_t*)(Ah + (kk * QT + q) * 16 + p)       = rep;
            *(uint32_t*)(Ah + ((kk + 4) * QT + q) * 16 + p) = imp;
        }
        __half* B0 = (__half*)(smem + BH_OFF);
        const uint2* Kg = (const uint2*)(g_Kh + (size_t)key0c * DIM);
        for (int idx = tid; idx < KT * 32; idx += 256) {
            int k = idx >> 5, j = idx & 31;
            uint2 v = Kg[idx];
            uint32_t rep = __byte_perm(v.x, v.y, 0x5410);
            uint32_t imp = __byte_perm(v.x, v.y, 0x7632);
            int kk = j >> 3, p = kperm_pair(j & 7);
            *(uint32_t*)(B0 + (kk * KT + k) * 16 + p)       = rep;
            *(uint32_t*)(B0 + ((kk + 4) * KT + k) * 16 + p) = imp;
        }
        // V: [256][8] gmem -> [256][12] smem (bank-conflict-free stride)
        const float2* Vg = (const float2*)(g_V + (size_t)key0c * 8);
        float2* Vf = (float2*)Vs;
        for (int idx = tid; idx < KEYS_PER_CTA * 3; idx += 256) {
            int r = idx / 3, c = idx - r * 3;
            Vf[r * 6 + c] = Vg[r * 4 + c];
        }
    }
    __syncthreads();

    int mrow0 = warpm * 32;

    float den[4] = {0.f, 0.f, 0.f, 0.f};
    float vacc[4][6];
    #pragma unroll
    for (int s = 0; s < 4; s++)
        #pragma unroll
        for (int c = 0; c < 6; c++) vacc[s][c] = 0.f;

    for (int kt = 0; kt < NT_TILES; kt++) {
        __half* Bh = (__half*)(smem + BH_OFF + (kt & 1) * BH_BYTES);

        // ---- prefetch next K tile into registers (LDG overlaps MMAs) ----
        uint2 kreg[8];
        if (kt + 1 < NT_TILES) {
            const uint2* Kg = (const uint2*)(g_Kh + (size_t)(key0c + (kt + 1) * KT) * DIM);
            #pragma unroll
            for (int i = 0; i < 8; i++) kreg[i] = Kg[tid + i * 256];
        }

        float re[2][4][4], im[2][4][4];
        #pragma unroll
        for (int mf = 0; mf < 2; mf++)
            #pragma unroll
            for (int nf = 0; nf < 4; nf++)
                #pragma unroll
                for (int e = 0; e < 4; e++) { re[mf][nf][e] = 0.f; im[mf][nf][e] = 0.f; }

        #pragma unroll
        for (int kp = 0; kp < 4; kp++) {
            // A fragments (4 b32 each): chunk kp = qr, chunk kp+4 = qi
            uint32_t aR[2][4], aI[2][4], aRn[2][4];
            #pragma unroll
            for (int mf = 0; mf < 2; mf++) {
                int rowA = mrow0 + mf * 16 + rr;
                uint2 lo, hi;
                lo = *(const uint2*)(Ah + (kp * QT + rowA) * 16 + 4 * cc);
                hi = *(const uint2*)(Ah + (kp * QT + rowA + 8) * 16 + 4 * cc);
                aR[mf][0] = lo.x; aR[mf][1] = hi.x; aR[mf][2] = lo.y; aR[mf][3] = hi.y;
                lo = *(const uint2*)(Ah + ((kp + 4) * QT + rowA) * 16 + 4 * cc);
                hi = *(const uint2*)(Ah + ((kp + 4) * QT + rowA + 8) * 16 + 4 * cc);
                aI[mf][0] = lo.x; aI[mf][1] = hi.x; aI[mf][2] = lo.y; aI[mf][3] = hi.y;
                #pragma unroll
                for (int e = 0; e < 4; e++) aRn[mf][e] = aR[mf][e] ^ 0x80008000u;
            }
            // B fragments (2 b32 each): chunk kp = kr, chunk kp+4 = ki
            uint2 bR[4], bI[4];
            #pragma unroll
            for (int nf = 0; nf < 4; nf++) {
                int keyB = warpn * 32 + nf * 8 + rr;
                bR[nf] = *(const uint2*)(Bh + (kp * KT + keyB) * 16 + 4 * cc);
                bI[nf] = *(const uint2*)(Bh + ((kp + 4) * KT + keyB) * 16 + 4 * cc);
            }
            #pragma unroll
            for (int mf = 0; mf < 2; mf++) {
                #pragma unroll
                for (int nf = 0; nf < 4; nf++) {
                    // re += qr.kr + qi.ki
                    mma_f16(re[mf][nf], aR[mf][0], aR[mf][1], aR[mf][2], aR[mf][3],
                            bR[nf].x, bR[nf].y);
                    mma_f16(re[mf][nf], aI[mf][0], aI[mf][1], aI[mf][2], aI[mf][3],
                            bI[nf].x, bI[nf].y);
                    // im += qi.kr - qr.ki
                    mma_f16(im[mf][nf], aI[mf][0], aI[mf][1], aI[mf][2], aI[mf][3],
                            bR[nf].x, bR[nf].y);
                    mma_f16(im[mf][nf], aRn[mf][0], aRn[mf][1], aRn[mf][2], aRn[mf][3],
                            bI[nf].x, bI[nf].y);
                }
            }
        }

        // ---- epilogue: w = exp(re^2 + im^2); accumulate w*V and w ----
        #pragma unroll
        for (int nf = 0; nf < 4; nf++) {
            int j0 = kt * KT + warpn * 32 + nf * 8 + 2 * cc;   // chunk-local key
            float vv[2][6];
            #pragma unroll
            for (int c = 0; c < 6; c++) {
                vv[0][c] = Vs[j0 * 12 + c];
                vv[1][c] = Vs[(j0 + 1) * 12 + c];
            }
            #pragma unroll
            for (int mf = 0; mf < 2; mf++) {
                #pragma unroll
                for (int e = 0; e < 4; e++) {
                    float r = re[mf][nf][e], i = im[mf][nf][e];
                    float l = fmaf(r, r, i * i);
                    float w = __expf(l);
                    int rs = mf * 2 + (e >> 1);
                    den[rs] += w;
                    const float* v = vv[e & 1];
                    #pragma unroll
                    for (int c = 0; c < 6; c++)
                        vacc[rs][c] = fmaf(w, v[c], vacc[rs][c]);
                }
            }
        }

        // ---- store prefetched tile into the other buffer (packed STS.32) ----
        if (kt + 1 < NT_TILES) {
            __half* Bn = (__half*)(smem + BH_OFF + ((kt + 1) & 1) * BH_BYTES);
            #pragma unroll
            for (int i = 0; i < 8; i++) {
                int idx = tid + i * 256;
                int k = idx >> 5, j = idx & 31;
                uint2 v = kreg[i];
                uint32_t rep = __byte_perm(v.x, v.y, 0x5410);
                uint32_t imp = __byte_perm(v.x, v.y, 0x7632);
                int kk = j >> 3, p = kperm_pair(j & 7);
                *(uint32_t*)(Bn + (kk * KT + k) * 16 + p)       = rep;
                *(uint32_t*)(Bn + ((kk + 4) * KT + k) * 16 + p) = imp;
            }
        }
        __syncthreads();
    }

    // reduce across the 4 lanes (cc) sharing each query row
    #pragma unroll
    for (int off = 1; off <= 2; off <<= 1) {
        #pragma unroll
        for (int s = 0; s < 4; s++) {
            den[s] += __shfl_xor_sync(0xffffffffu, den[s], off);
            #pragma unroll
            for (int c = 0; c < 6; c++)
                vacc[s][c] += __shfl_xor_sync(0xffffffffu, vacc[s][c], off);
        }
    }
    if (cc == 0) {
        int slot = blockIdx.y * 2 + warpn;
        #pragma unroll
        for (int mf = 0; mf < 2; mf++) {
            #pragma unroll
            for (int h = 0; h < 2; h++) {
                int s  = mf * 2 + h;
                int qi = q0 + mrow0 + mf * 16 + h * 8 + rr;
                #pragma unroll
                for (int c = 0; c < 6; c++) g_part[qi][slot][c] = vacc[s][c];
                g_part[qi][slot][6] = den[s];
            }
        }
    }
}

// ---------------------------------------------------------------------------
// Phase 3: deterministic combine — one warp per token, coalesced float4 reads.
// Lane l reduces slots {l, l+32}; butterfly-reduce 7 values; lane 0 writes.
// ---------------------------------------------------------------------------
__global__ void __launch_bounds__(256) finalize_kernel(float* __restrict__ out)
{
    int wid  = threadIdx.x >> 5;
    int lane = threadIdx.x & 31;
    int tok  = blockIdx.x * 8 + wid;
    if (tok >= NTOK) return;

    float num[6] = {0.f, 0.f, 0.f, 0.f, 0.f, 0.f};
    float den = 0.f;
    #pragma unroll
    for (int h = 0; h < 2; h++) {
        int s = lane + h * 32;
        float4 a = *(const float4*)&g_part[tok][s][0];
        float4 b = *(const float4*)&g_part[tok][s][4];
        num[0] += a.x; num[1] += a.y; num[2] += a.z; num[3] += a.w;
        num[4] += b.x; num[5] += b.y; den += b.z;
    }
    #pragma unroll
    for (int off = 16; off >= 1; off >>= 1) {
        den += __shfl_xor_sync(0xffffffffu, den, off);
        #pragma unroll
        for (int c = 0; c < 6; c++)
            num[c] += __shfl_xor_sync(0xffffffffu, num[c], off);
    }
    if (lane == 0) {
        float inv = 1.f / den;
        #pragma unroll
        for (int c = 0; c < 6; c++) out[tok * 6 + c] = num[c] * inv;
    }
}

// ---------------------------------------------------------------------------
extern "C" void kernel_launch(void* const* d_in, const int* in_sizes, int n_in,
                              void* d_out, int out_size)
{
    const float* x  = (const float*)d_in[0];  // (8192, 6)
    const float* pq = (const float*)d_in[1];  // (2, 6, 2)
    const float* pk = (const float*)d_in[2];
    const float* pv = (const float*)d_in[3];
    float* out = (float*)d_out;               // (8192, 6) f32

    trig_kernel<<<1, 128>>>(pq, pk, pv);
    prep_kernel<<<(NTOK * 3) / 8, 256>>>(x);

    cudaFuncSetAttribute(attn_kernel, cudaFuncAttributeMaxDynamicSharedMemorySize, SMEM_BYTES);
    attn_kernel<<<dim3(NTOK / QT, KSPL), 256, SMEM_BYTES>>>();

    // warp-per-token: 8 tokens per 256-thread block -> NTOK/8 blocks
    finalize_kernel<<<NTOK / 8, 256>>>(out);
}

// round 16
// speedup vs baseline: 1.1428x; 1.1428x over previous
#include <cuda_runtime.h>
#include <cuda_fp16.h>
#include <cstdint>

// ============================================================================
// SwapTestAttention on GB300 — Round 15: exact-2-wave flat tile decomposition.
//   Work space = 64 qtiles x 128 ktiles = 8192 flat tile-units.
//   608 CTAs (= 2 waves at 2 CTAs/SM x 152 SMs) each own a contiguous flat
//   range (13-14 tiles, at most one qtile boundary -> at most one A reload).
//   Pipeline per tile identical to the proven R11 kernel (double-buffered K+V,
//   register prefetch, packed STS.32). Partials: <=12 CTAs cover a qtile ->
//   24 slots/token (pre-zeroed), summed by warp-per-token finalize.
// ============================================================================

#define NTOK 8192
#define NQB  6
#define DIM  64
#define NL   2

#define QT   128                 // queries per qtile (A tile rows)
#define KT   64                  // keys per tile
#define NQT  (NTOK / QT)         // 64 qtiles
#define NKT  (NTOK / KT)         // 128 ktiles
#define NT_TOTAL (NQT * NKT)     // 8192 flat tile-units
#define NCTA 608                 // 2 waves x 2 CTAs/SM x 152 SMs
#define NSLOT 24                 // <=12 covering CTAs x 2 n-warps

// smem byte offsets
#define AH_BYTES  (8 * QT * 16 * 2)          // 32768: A chunks [8][128][16] half
#define BH_BYTES  (8 * KT * 16 * 2)          // 16384 per buffer
#define BH_OFF    AH_BYTES                   // two buffers: 32768 total
#define VS_OFF    (AH_BYTES + 2 * BH_BYTES)  // V [2][64][12] float = 6144
#define SMEM_BYTES (VS_OFF + 2 * KT * 12 * 4)   // 71680

// Scratch (device globals; no allocation allowed)
__device__ __half2 g_Qh[NTOK * DIM];         // [token][64] (re,im)
__device__ __half2 g_Kh[NTOK * DIM];
__device__ float   g_V[NTOK * 8];            // 6 used + pad
__device__ float   g_part[NTOK][NSLOT][8];   // token-major partials (6 acc + den + pad)
__device__ float   g_trig[3 * NL * NQB * 2 * 2];  // [role][l][q][gate][{s,c}]

__device__ __forceinline__ float shfl_x(float v, int m) {
    return __shfl_xor_sync(0xffffffffu, v, m);
}
__device__ __forceinline__ void mma_f16(float d[4],
    uint32_t a0, uint32_t a1, uint32_t a2, uint32_t a3,
    uint32_t b0, uint32_t b1)
{
    asm volatile(
        "mma.sync.aligned.m16n8k16.row.col.f32.f16.f16.f32 "
        "{%0,%1,%2,%3}, {%4,%5,%6,%7}, {%8,%9}, {%0,%1,%2,%3};"
        : "+f"(d[0]), "+f"(d[1]), "+f"(d[2]), "+f"(d[3])
        : "r"(a0), "r"(a1), "r"(a2), "r"(a3), "r"(b0), "r"(b1));
}
__device__ __forceinline__ int kperm_pair(int j) {   // position of col 2j
    return 4 * (j & 3) + 2 * (j >> 2);
}
// CTA owning flat tile T (inverse of t0(c) = floor(c*NT_TOTAL/NCTA))
__device__ __forceinline__ int cta_of_tile(int T) {
    return (int)(((long long)(T + 1) * NCTA - 1) / NT_TOTAL);
}

// ---------------------------------------------------------------------------
// Phase 0a: precompute sin/cos of all 72 param gate half-angles (3 roles).
// ---------------------------------------------------------------------------
__global__ void trig_kernel(const float* __restrict__ pq,
                            const float* __restrict__ pk,
                            const float* __restrict__ pv)
{
    int t = threadIdx.x;
    if (t >= 3 * NL * NQB * 2) return;
    int role = t / (NL * NQB * 2);
    int g    = t - role * (NL * NQB * 2);
    const float* p = (role == 0) ? pq : (role == 1) ? pk : pv;
    float s, c; __sincosf(0.5f * p[g], &s, &c);
    g_trig[t * 2 + 0] = s;
    g_trig[t * 2 + 1] = c;
}

// Phase 0b: zero the partials table (slots not covered stay zero).
__global__ void zero_kernel()
{
    float4* p = (float4*)g_part;
    int i = blockIdx.x * 256 + threadIdx.x;
    if (i < NTOK * NSLOT * 2) p[i] = make_float4(0.f, 0.f, 0.f, 0.f);
}

// ---------------------------------------------------------------------------
// Phase 1: one warp simulates one (token, role) circuit.
// ---------------------------------------------------------------------------
__global__ void __launch_bounds__(256) prep_kernel(
    const float* __restrict__ x)
{
    int gw    = (blockIdx.x * 256 + threadIdx.x) >> 5;
    int lane  = threadIdx.x & 31;
    int token = gw & (NTOK - 1);
    int role  = gw >> 13;                  // 0=Q, 1=K, 2=V
    const float* tg = g_trig + role * (NL * NQB * 2 * 2);

    float r0 = (lane == 0) ? 1.f : 0.f, i0 = 0.f, r1 = 0.f, i1 = 0.f;

    auto RYsc = [&](float s, float c, int q) {
        if (q == 0) {
            float nr0 = c*r0 - s*r1, ni0 = c*i0 - s*i1;
            float nr1 = s*r0 + c*r1, ni1 = s*i0 + c*i1;
            r0 = nr0; i0 = ni0; r1 = nr1; i1 = ni1;
        } else {
            int m = 1 << (5 - q);
            float pr0 = shfl_x(r0, m), pi0 = shfl_x(i0, m);
            float pr1 = shfl_x(r1, m), pi1 = shfl_x(i1, m);
            float sg = (lane & m) ? s : -s;
            r0 = fmaf(sg, pr0, c*r0); i0 = fmaf(sg, pi0, c*i0);
            r1 = fmaf(sg, pr1, c*r1); i1 = fmaf(sg, pi1, c*i1);
        }
    };
    auto RZsc = [&](float s, float c, int q) {
        if (q == 0) {
            float nr0 = r0*c + i0*s, ni0 = i0*c - r0*s;
            float nr1 = r1*c - i1*s, ni1 = i1*c + r1*s;
            r0 = nr0; i0 = ni0; r1 = nr1; i1 = ni1;
        } else {
            int m = 1 << (5 - q);
            float sg = (lane & m) ? s : -s;
            float nr0 = r0*c - i0*sg, ni0 = i0*c + r0*sg;
            float nr1 = r1*c - i1*sg, ni1 = i1*c + r1*sg;
            r0 = nr0; i0 = ni0; r1 = nr1; i1 = ni1;
        }
    };

    #pragma unroll
    for (int q = 0; q < NQB; q++) {
        float s, c; __sincosf(0.5f * x[token * NQB + q], &s, &c);
        RYsc(s, c, q);
    }

    #pragma unroll
    for (int l = 0; l < NL; l++) {
        #pragma unroll
        for (int q = 0; q < NQB; q++) {
            int base = ((l * NQB + q) * 2) * 2;
            RYsc(tg[base + 0], tg[base + 1], q);
            RZsc(tg[base + 2], tg[base + 3], q);
        }
        r1 = shfl_x(r1, 16); i1 = shfl_x(i1, 16);
        #pragma unroll
        for (int q = 1; q <= 4; q++) {
            int cm = 1 << (5 - q), tm = 1 << (4 - q);
            float t;
            t = shfl_x(r0, tm); if (lane & cm) r0 = t;
            t = shfl_x(i0, tm); if (lane & cm) i0 = t;
            t = shfl_x(r1, tm); if (lane & cm) r1 = t;
            t = shfl_x(i1, tm); if (lane & cm) i1 = t;
        }
        if (lane & 1) { float t = r0; r0 = r1; r1 = t; t = i0; i0 = i1; i1 = t; }
    }

    if (role < 2) {
        __half2* buf = (role == 0) ? g_Qh : g_Kh;
        buf[token * DIM + lane]      = __floats2half2_rn(r0, i0);
        buf[token * DIM + 32 + lane] = __floats2half2_rn(r1, i1);
    } else {
        float p0 = r0*r0 + i0*i0;
        float p1 = r1*r1 + i1*i1;
        float v[6];
        v[0] = p0 - p1;
        #pragma unroll
        for (int q = 1; q < 6; q++) {
            float sgn = ((lane >> (5 - q)) & 1) ? -1.f : 1.f;
            v[q] = sgn * (p0 + p1);
        }
        #pragma unroll
        for (int off = 16; off >= 1; off >>= 1) {
            #pragma unroll
            for (int q = 0; q < 6; q++) v[q] += __shfl_down_sync(0xffffffffu, v[q], off);
        }
        if (lane == 0) {
            #pragma unroll
            for (int q = 0; q < 6; q++) g_V[token * 8 + q] = v[q];
            g_V[token * 8 + 6] = 0.f;
            g_V[token * 8 + 7] = 0.f;
        }
    }
}

// ---------------------------------------------------------------------------
// Phase 2: fp16 m16n8k16 fused attention over a flat tile range.
// ---------------------------------------------------------------------------
__global__ void __launch_bounds__(256, 2) attn_kernel()
{
    extern __shared__ char smem[];
    __half* Ah = (__half*)smem;                 // [8][QT][16]
    float*  Vs = (float*)(smem + VS_OFF);       // [2][64][12]

    int tid   = threadIdx.x;
    int lane  = tid & 31;
    int wid   = tid >> 5;
    int warpm = wid & 3;
    int warpn = wid >> 2;
    int rr    = lane >> 2;       // 0..7
    int cc    = lane & 3;        // 0..3
    int c     = blockIdx.x;

    int t0 = (int)(((long long)c * NT_TOTAL) / NCTA);
    int t1 = (int)(((long long)(c + 1) * NT_TOTAL) / NCTA);
    int qt = t0 >> 7;            // current qtile
    int mrow0 = warpm * 32;

    // ---- A tile loader (Q) ----
    auto load_A = [&](int q) {
        const uint2* Qg = (const uint2*)(g_Qh + (size_t)(q * QT) * DIM);
        for (int idx = tid; idx < QT * 32; idx += 256) {
            int r = idx >> 5, j = idx & 31;               // dims 2j, 2j+1
            uint2 v = Qg[idx];
            uint32_t rep = __byte_perm(v.x, v.y, 0x5410);
            uint32_t imp = __byte_perm(v.x, v.y, 0x7632);
            int kk = j >> 3, p = kperm_pair(j & 7);
            *(uint32_t*)(Ah + (kk * QT + r) * 16 + p)       = rep;
            *(uint32_t*)(Ah + ((kk + 4) * QT + r) * 16 + p) = imp;
        }
    };

    // ---- prologue: A tile, first B tile + V tile (buffer 0) ----
    load_A(qt);
    {
        int key0 = (t0 & 127) * KT;
        __half* B0 = (__half*)(smem + BH_OFF);
        const uint2* Kg = (const uint2*)(g_Kh + (size_t)key0 * DIM);
        for (int idx = tid; idx < KT * 32; idx += 256) {
            int k = idx >> 5, j = idx & 31;
            uint2 v = Kg[idx];
            uint32_t rep = __byte_perm(v.x, v.y, 0x5410);
            uint32_t imp = __byte_perm(v.x, v.y, 0x7632);
            int kk = j >> 3, p = kperm_pair(j & 7);
            *(uint32_t*)(B0 + (kk * KT + k) * 16 + p)       = rep;
            *(uint32_t*)(B0 + ((kk + 4) * KT + k) * 16 + p) = imp;
        }
        if (tid < KT * 2) {      // 64 rows x 2 float4
            float4 v = ((const float4*)(g_V + (size_t)key0 * 8))[tid];
            int r = tid >> 1, h = tid & 1;
            *(float4*)(Vs + r * 12 + h * 4) = v;
        }
    }
    __syncthreads();

    float den[4] = {0.f, 0.f, 0.f, 0.f};
    float vacc[4][6];
    #pragma unroll
    for (int s = 0; s < 4; s++)
        #pragma unroll
        for (int cq = 0; cq < 6; cq++) vacc[s][cq] = 0.f;

    // ---- flush accumulators for qtile q into g_part, then reset ----
    auto flush = [&](int q) {
        #pragma unroll
        for (int off = 1; off <= 2; off <<= 1) {
            #pragma unroll
            for (int s = 0; s < 4; s++) {
                den[s] += __shfl_xor_sync(0xffffffffu, den[s], off);
                #pragma unroll
                for (int cq = 0; cq < 6; cq++)
                    vacc[s][cq] += __shfl_xor_sync(0xffffffffu, vacc[s][cq], off);
            }
        }
        if (cc == 0) {
            int slot = (c - cta_of_tile(q * 128)) * 2 + warpn;
            #pragma unroll
            for (int mf = 0; mf < 2; mf++) {
                #pragma unroll
                for (int h = 0; h < 2; h++) {
                    int s  = mf * 2 + h;
                    int qi = q * QT + mrow0 + mf * 16 + h * 8 + rr;
                    #pragma unroll
                    for (int cq = 0; cq < 6; cq++) g_part[qi][slot][cq] = vacc[s][cq];
                    g_part[qi][slot][6] = den[s];
                }
            }
        }
        #pragma unroll
        for (int s = 0; s < 4; s++) {
            den[s] = 0.f;
            #pragma unroll
            for (int cq = 0; cq < 6; cq++) vacc[s][cq] = 0.f;
        }
    };

    for (int t = t0; t < t1; t++) {
        int buf = (t - t0) & 1;
        __half* Bh = (__half*)(smem + BH_OFF + buf * BH_BYTES);
        bool has_next = (t + 1 < t1);

        // ---- prefetch next tile's K + V into registers ----
        uint2 kreg[8];
        float4 vreg;
        if (has_next) {
            int key0n = ((t + 1) & 127) * KT;
            const uint2* Kg = (const uint2*)(g_Kh + (size_t)key0n * DIM);
            #pragma unroll
            for (int i = 0; i < 8; i++) kreg[i] = Kg[tid + i * 256];
            if (tid < KT * 2)
                vreg = ((const float4*)(g_V + (size_t)key0n * 8))[tid];
        }

        float re[2][4][4], im[2][4][4];
        #pragma unroll
        for (int mf = 0; mf < 2; mf++)
            #pragma unroll
            for (int nf = 0; nf < 4; nf++)
                #pragma unroll
                for (int e = 0; e < 4; e++) { re[mf][nf][e] = 0.f; im[mf][nf][e] = 0.f; }

        #pragma unroll
        for (int kp = 0; kp < 4; kp++) {
            uint32_t aR[2][4], aI[2][4], aRn[2][4];
            #pragma unroll
            for (int mf = 0; mf < 2; mf++) {
                int rowA = mrow0 + mf * 16 + rr;
                uint2 lo, hi;
                lo = *(const uint2*)(Ah + (kp * QT + rowA) * 16 + 4 * cc);
                hi = *(const uint2*)(Ah + (kp * QT + rowA + 8) * 16 + 4 * cc);
                aR[mf][0] = lo.x; aR[mf][1] = hi.x; aR[mf][2] = lo.y; aR[mf][3] = hi.y;
                lo = *(const uint2*)(Ah + ((kp + 4) * QT + rowA) * 16 + 4 * cc);
                hi = *(const uint2*)(Ah + ((kp + 4) * QT + rowA + 8) * 16 + 4 * cc);
                aI[mf][0] = lo.x; aI[mf][1] = hi.x; aI[mf][2] = lo.y; aI[mf][3] = hi.y;
                #pragma unroll
                for (int e = 0; e < 4; e++) aRn[mf][e] = aR[mf][e] ^ 0x80008000u;
            }
            uint2 bR[4], bI[4];
            #pragma unroll
            for (int nf = 0; nf < 4; nf++) {
                int keyB = warpn * 32 + nf * 8 + rr;
                bR[nf] = *(const uint2*)(Bh + (kp * KT + keyB) * 16 + 4 * cc);
                bI[nf] = *(const uint2*)(Bh + ((kp + 4) * KT + keyB) * 16 + 4 * cc);
            }
            #pragma unroll
            for (int mf = 0; mf < 2; mf++) {
                #pragma unroll
                for (int nf = 0; nf < 4; nf++) {
                    mma_f16(re[mf][nf], aR[mf][0], aR[mf][1], aR[mf][2], aR[mf][3],
                            bR[nf].x, bR[nf].y);
                    mma_f16(re[mf][nf], aI[mf][0], aI[mf][1], aI[mf][2], aI[mf][3],
                            bI[nf].x, bI[nf].y);
                    mma_f16(im[mf][nf], aI[mf][0], aI[mf][1], aI[mf][2], aI[mf][3],
                            bR[nf].x, bR[nf].y);
                    mma_f16(im[mf][nf], aRn[mf][0], aRn[mf][1], aRn[mf][2], aRn[mf][3],
                            bI[nf].x, bI[nf].y);
                }
            }
        }

        // ---- epilogue: w = exp(re^2 + im^2); accumulate w*V and w ----
        const float* Vb = Vs + buf * (KT * 12);
        #pragma unroll
        for (int nf = 0; nf < 4; nf++) {
            int j0 = warpn * 32 + nf * 8 + 2 * cc;    // tile-local key
            float vv[2][6];
            #pragma unroll
            for (int cq = 0; cq < 6; cq++) {
                vv[0][cq] = Vb[j0 * 12 + cq];
                vv[1][cq] = Vb[(j0 + 1) * 12 + cq];
            }
            #pragma unroll
            for (int mf = 0; mf < 2; mf++) {
                #pragma unroll
                for (int e = 0; e < 4; e++) {
                    float r = re[mf][nf][e], i = im[mf][nf][e];
                    float l = fmaf(r, r, i * i);
                    float w = __expf(l);
                    int rs = mf * 2 + (e >> 1);
                    den[rs] += w;
                    const float* v = vv[e & 1];
                    #pragma unroll
                    for (int cq = 0; cq < 6; cq++)
                        vacc[rs][cq] = fmaf(w, v[cq], vacc[rs][cq]);
                }
            }
        }

        // ---- store prefetched tile into the other buffer ----
        if (has_next) {
            __half* Bn = (__half*)(smem + BH_OFF + (buf ^ 1) * BH_BYTES);
            #pragma unroll
            for (int i = 0; i < 8; i++) {
                int idx = tid + i * 256;
                int k = idx >> 5, j = idx & 31;
                uint2 v = kreg[i];
                uint32_t rep = __byte_perm(v.x, v.y, 0x5410);
                uint32_t imp = __byte_perm(v.x, v.y, 0x7632);
                int kk = j >> 3, p = kperm_pair(j & 7);
                *(uint32_t*)(Bn + (kk * KT + k) * 16 + p)       = rep;
                *(uint32_t*)(Bn + ((kk + 4) * KT + k) * 16 + p) = imp;
            }
            if (tid < KT * 2) {
                int r = tid >> 1, h = tid & 1;
                *(float4*)(Vs + (buf ^ 1) * (KT * 12) + r * 12 + h * 4) = vreg;
            }
        }
        __syncthreads();

        // ---- qtile boundary: flush + reload A ----
        if (has_next && ((t + 1) >> 7) != qt) {
            flush(qt);
            qt = (t + 1) >> 7;
            load_A(qt);
            __syncthreads();
        }
    }
    flush(qt);
}

// ---------------------------------------------------------------------------
// Phase 3: deterministic combine — one warp per token; lanes 0..23 own slots.
// ---------------------------------------------------------------------------
__global__ void __launch_bounds__(256) finalize_kernel(float* __restrict__ out)
{
    int wid  = threadIdx.x >> 5;
    int lane = threadIdx.x & 31;
    int tok  = blockIdx.x * 8 + wid;
    if (tok >= NTOK) return;

    float num[6] = {0.f, 0.f, 0.f, 0.f, 0.f, 0.f};
    float den = 0.f;
    if (lane < NSLOT) {
        float4 a = *(const float4*)&g_part[tok][lane][0];
        float4 b = *(const float4*)&g_part[tok][lane][4];
        num[0] = a.x; num[1] = a.y; num[2] = a.z; num[3] = a.w;
        num[4] = b.x; num[5] = b.y; den = b.z;
    }
    #pragma unroll
    for (int off = 16; off >= 1; off >>= 1) {
        den += __shfl_xor_sync(0xffffffffu, den, off);
        #pragma unroll
        for (int c = 0; c < 6; c++)
            num[c] += __shfl_xor_sync(0xffffffffu, num[c], off);
    }
    if (lane == 0) {
        float inv = 1.f / den;
        #pragma unroll
        for (int c = 0; c < 6; c++) out[tok * 6 + c] = num[c] * inv;
    }
}

// ---------------------------------------------------------------------------
extern "C" void kernel_launch(void* const* d_in, const int* in_sizes, int n_in,
                              void* d_out, int out_size)
{
    const float* x  = (const float*)d_in[0];  // (8192, 6)
    const float* pq = (const float*)d_in[1];  // (2, 6, 2)
    const float* pk = (const float*)d_in[2];
    const float* pv = (const float*)d_in[3];
    float* out = (float*)d_out;               // (8192, 6) f32

    trig_kernel<<<1, 128>>>(pq, pk, pv);
    zero_kernel<<<(NTOK * NSLOT * 2 + 255) / 256, 256>>>();
    prep_kernel<<<(NTOK * 3) / 8, 256>>>(x);

    cudaFuncSetAttribute(attn_kernel, cudaFuncAttributeMaxDynamicSharedMemorySize, SMEM_BYTES);
    attn_kernel<<<NCTA, 256, SMEM_BYTES>>>();

    finalize_kernel<<<NTOK / 8, 256>>>(out);
}